// round 6
// baseline (speedup 1.0000x reference)
#include <cuda_runtime.h>
#include <cuda_bf16.h>

// Problem: B=4, S=4096, E=512
//   q = query @ Wq^T + bq ; k,v likewise
//   scores = q @ k^T (NO 1/sqrt(d) scale), softmax rows, out = P @ v
//
// Stage pipeline (all fp32):
//   1) gemm_abt  x3 batched (z=0,1,2)  : QKV projections -> g_q/g_k/g_v
//   2) gemm_abt  batched over 4 batches: scores = q @ k^T -> g_s (256 MB)
//   3) softmax_rows over 16384 rows of 4096
//   4) gemm_ab   batched over 4 batches: out = P @ v -> d_out

#define BM 128
#define BN 128
#define BK 16
#define SPAD 4   // smem row padding (floats)

// Scratch (device globals: allocation-free per harness rules)
__device__ float g_q[16384 * 512];
__device__ float g_k[16384 * 512];
__device__ float g_v[16384 * 512];
__device__ float g_s[(size_t)4 * 4096 * 4096];   // 256 MB

// ---------------------------------------------------------------------------
// C[M,N] = A[M,K] @ B[N,K]^T (+ bias[N]), batched via blockIdx.z with strides.
// Both A and B are row-major with K contiguous (exactly x @ W^T and q @ k^T).
// ---------------------------------------------------------------------------
__global__ __launch_bounds__(256, 2)
void gemm_abt(const float* __restrict__ A, const float* __restrict__ B,
              const float* __restrict__ bias, float* __restrict__ C,
              int M, int N, int K,
              long sA, long sB, long sC)
{
    __shared__ float As[BK][BM + SPAD];
    __shared__ float Bs[BK][BN + SPAD];

    long z = blockIdx.z;
    A += z * sA;  B += z * sB;  C += z * sC;

    const int row0 = blockIdx.y * BM;
    const int col0 = blockIdx.x * BN;
    const int t  = threadIdx.x;       // 0..255
    const int ty = t >> 4;            // 0..15 -> output rows ty*4, 64+ty*4
    const int tx = t & 15;            // 0..15 -> output cols tx*4, 64+tx*4

    const int lr = t >> 2;            // 0..63  load row
    const int lc = (t & 3) * 4;       // 0,4,8,12 load k-offset

    float acc[8][8];
    #pragma unroll
    for (int i = 0; i < 8; i++)
        #pragma unroll
        for (int j = 0; j < 8; j++) acc[i][j] = 0.f;

    for (int k0 = 0; k0 < K; k0 += BK) {
        #pragma unroll
        for (int h = 0; h < 2; h++) {
            int r = lr + h * 64;
            float4 va = *reinterpret_cast<const float4*>(&A[(long)(row0 + r) * K + k0 + lc]);
            As[lc + 0][r] = va.x; As[lc + 1][r] = va.y;
            As[lc + 2][r] = va.z; As[lc + 3][r] = va.w;
            float4 vb = *reinterpret_cast<const float4*>(&B[(long)(col0 + r) * K + k0 + lc]);
            Bs[lc + 0][r] = vb.x; Bs[lc + 1][r] = vb.y;
            Bs[lc + 2][r] = vb.z; Bs[lc + 3][r] = vb.w;
        }
        __syncthreads();

        #pragma unroll
        for (int kk = 0; kk < BK; kk++) {
            float a[8], b[8];
            *reinterpret_cast<float4*>(a)     = *reinterpret_cast<const float4*>(&As[kk][ty * 4]);
            *reinterpret_cast<float4*>(a + 4) = *reinterpret_cast<const float4*>(&As[kk][64 + ty * 4]);
            *reinterpret_cast<float4*>(b)     = *reinterpret_cast<const float4*>(&Bs[kk][tx * 4]);
            *reinterpret_cast<float4*>(b + 4) = *reinterpret_cast<const float4*>(&Bs[kk][64 + tx * 4]);
            #pragma unroll
            for (int i = 0; i < 8; i++)
                #pragma unroll
                for (int j = 0; j < 8; j++)
                    acc[i][j] = fmaf(a[i], b[j], acc[i][j]);
        }
        __syncthreads();
    }

    #pragma unroll
    for (int i = 0; i < 8; i++) {
        int r = row0 + ((i < 4) ? (ty * 4 + i) : (64 + ty * 4 + (i - 4)));
        #pragma unroll
        for (int jh = 0; jh < 2; jh++) {
            int c = col0 + jh * 64 + tx * 4;
            float4 v;
            v.x = acc[i][jh * 4 + 0]; v.y = acc[i][jh * 4 + 1];
            v.z = acc[i][jh * 4 + 2]; v.w = acc[i][jh * 4 + 3];
            if (bias) {
                v.x += bias[c + 0]; v.y += bias[c + 1];
                v.z += bias[c + 2]; v.w += bias[c + 3];
            }
            *reinterpret_cast<float4*>(&C[(long)r * N + c]) = v;
        }
    }
}

// ---------------------------------------------------------------------------
// C[M,N] = A[M,K] @ B[K,N], batched via blockIdx.z. (out = P @ v)
// ---------------------------------------------------------------------------
__global__ __launch_bounds__(256, 2)
void gemm_ab(const float* __restrict__ A, const float* __restrict__ B,
             float* __restrict__ C,
             int M, int N, int K,
             long sA, long sB, long sC)
{
    __shared__ float As[BK][BM + SPAD];
    __shared__ float Bs[BK][BN + SPAD];

    long z = blockIdx.z;
    A += z * sA;  B += z * sB;  C += z * sC;

    const int row0 = blockIdx.y * BM;
    const int col0 = blockIdx.x * BN;
    const int t  = threadIdx.x;
    const int ty = t >> 4;
    const int tx = t & 15;

    const int lr = t >> 2;            // A load row 0..63
    const int lc = (t & 3) * 4;       // A load k-offset
    const int bc = t >> 5;            // B load k-row 0..7
    const int bn = (t & 31) * 4;      // B load col offset 0..124

    float acc[8][8];
    #pragma unroll
    for (int i = 0; i < 8; i++)
        #pragma unroll
        for (int j = 0; j < 8; j++) acc[i][j] = 0.f;

    for (int k0 = 0; k0 < K; k0 += BK) {
        #pragma unroll
        for (int h = 0; h < 2; h++) {
            int r = lr + h * 64;
            float4 va = *reinterpret_cast<const float4*>(&A[(long)(row0 + r) * K + k0 + lc]);
            As[lc + 0][r] = va.x; As[lc + 1][r] = va.y;
            As[lc + 2][r] = va.z; As[lc + 3][r] = va.w;
            int c = bc + h * 8;
            float4 vb = *reinterpret_cast<const float4*>(&B[(long)(k0 + c) * N + col0 + bn]);
            *reinterpret_cast<float4*>(&Bs[c][bn]) = vb;
        }
        __syncthreads();

        #pragma unroll
        for (int kk = 0; kk < BK; kk++) {
            float a[8], b[8];
            *reinterpret_cast<float4*>(a)     = *reinterpret_cast<const float4*>(&As[kk][ty * 4]);
            *reinterpret_cast<float4*>(a + 4) = *reinterpret_cast<const float4*>(&As[kk][64 + ty * 4]);
            *reinterpret_cast<float4*>(b)     = *reinterpret_cast<const float4*>(&Bs[kk][tx * 4]);
            *reinterpret_cast<float4*>(b + 4) = *reinterpret_cast<const float4*>(&Bs[kk][64 + tx * 4]);
            #pragma unroll
            for (int i = 0; i < 8; i++)
                #pragma unroll
                for (int j = 0; j < 8; j++)
                    acc[i][j] = fmaf(a[i], b[j], acc[i][j]);
        }
        __syncthreads();
    }

    #pragma unroll
    for (int i = 0; i < 8; i++) {
        int r = row0 + ((i < 4) ? (ty * 4 + i) : (64 + ty * 4 + (i - 4)));
        #pragma unroll
        for (int jh = 0; jh < 2; jh++) {
            int c = col0 + jh * 64 + tx * 4;
            float4 v;
            v.x = acc[i][jh * 4 + 0]; v.y = acc[i][jh * 4 + 1];
            v.z = acc[i][jh * 4 + 2]; v.w = acc[i][jh * 4 + 3];
            *reinterpret_cast<float4*>(&C[(long)r * N + c]) = v;
        }
    }
}

// ---------------------------------------------------------------------------
// In-place row softmax: 16384 rows of 4096. One block (256 thr) per row.
// ---------------------------------------------------------------------------
__global__ __launch_bounds__(256)
void softmax_rows(float* __restrict__ S)
{
    const long row = blockIdx.x;
    float4* p = reinterpret_cast<float4*>(S + row * 4096L);
    const int t = threadIdx.x;

    float4 v[4];
    float m = -1e30f;
    #pragma unroll
    for (int i = 0; i < 4; i++) {
        v[i] = p[t + i * 256];
        m = fmaxf(m, fmaxf(fmaxf(v[i].x, v[i].y), fmaxf(v[i].z, v[i].w)));
    }

    __shared__ float red[256];
    red[t] = m;
    __syncthreads();
    #pragma unroll
    for (int s = 128; s > 0; s >>= 1) {
        if (t < s) red[t] = fmaxf(red[t], red[t + s]);
        __syncthreads();
    }
    m = red[0];
    __syncthreads();

    float sum = 0.f;
    #pragma unroll
    for (int i = 0; i < 4; i++) {
        v[i].x = __expf(v[i].x - m); v[i].y = __expf(v[i].y - m);
        v[i].z = __expf(v[i].z - m); v[i].w = __expf(v[i].w - m);
        sum += (v[i].x + v[i].y) + (v[i].z + v[i].w);
    }
    red[t] = sum;
    __syncthreads();
    #pragma unroll
    for (int s = 128; s > 0; s >>= 1) {
        if (t < s) red[t] += red[t + s];
        __syncthreads();
    }
    const float inv = 1.0f / red[0];

    #pragma unroll
    for (int i = 0; i < 4; i++) {
        v[i].x *= inv; v[i].y *= inv; v[i].z *= inv; v[i].w *= inv;
        p[t + i * 256] = v[i];
    }
}

// ---------------------------------------------------------------------------
extern "C" void kernel_launch(void* const* d_in, const int* in_sizes, int n_in,
                              void* d_out, int out_size)
{
    const float* query = (const float*)d_in[0];
    const float* key   = (const float*)d_in[1];
    const float* value = (const float*)d_in[2];
    const float* Wq    = (const float*)d_in[3];
    const float* bq    = (const float*)d_in[4];
    const float* Wk    = (const float*)d_in[5];
    const float* bk    = (const float*)d_in[6];
    const float* Wv    = (const float*)d_in[7];
    const float* bv    = (const float*)d_in[8];
    float* out = (float*)d_out;

    float *qp, *kp, *vp, *sp;
    cudaGetSymbolAddress((void**)&qp, g_q);
    cudaGetSymbolAddress((void**)&kp, g_k);
    cudaGetSymbolAddress((void**)&vp, g_v);
    cudaGetSymbolAddress((void**)&sp, g_s);

    const int Btot = 4, S = 4096, E = 512;
    const int M = Btot * S;  // 16384

    dim3 thr(256);

    // 1) QKV projections: [16384,512] @ [512,512]^T + bias
    {
        dim3 grid(E / BN, M / BM, 1);
        gemm_abt<<<grid, thr>>>(query, Wq, bq, qp, M, E, E, 0, 0, 0);
        gemm_abt<<<grid, thr>>>(key,   Wk, bk, kp, M, E, E, 0, 0, 0);
        gemm_abt<<<grid, thr>>>(value, Wv, bv, vp, M, E, E, 0, 0, 0);
    }

    // 2) scores = q @ k^T per batch: [4096,512] @ [4096,512]^T
    {
        dim3 grid(S / BN, S / BM, Btot);
        gemm_abt<<<grid, thr>>>(qp, kp, nullptr, sp, S, S, E,
                                (long)S * E, (long)S * E, (long)S * S);
    }

    // 3) softmax over rows
    softmax_rows<<<M, thr>>>(sp);

    // 4) out = P @ v per batch: [4096,4096] @ [4096,512]
    {
        dim3 grid(E / BN, S / BM, Btot);
        gemm_ab<<<grid, thr>>>(sp, vp, out, S, E, S,
                               (long)S * S, (long)S * E, (long)S * E);
    }
}

// round 13
// speedup vs baseline: 2.2697x; 2.2697x over previous
#include <cuda_runtime.h>
#include <cuda_bf16.h>
#include <cstdint>

// B=4, S=4096, E=512.
// All GEMMs via mma.sync m16n8k16 bf16 (HMMA) with hi/lo split (3-term), fp32 acc.
//   split inputs -> gemm(+bias) -> q,k as bf16 hi/lo directly (fused epilogue)
//   v -> fp32 -> transpose_split -> V^T hi/lo
//   scores = q@k^T (fp32, 256MB) -> softmax_split -> P hi/lo
//   out = P@V   (B operand = V^T, K-major)

#define NSTAGE 3
#define SMEM_BYTES (NSTAGE * 32768)

// ----------------------------- scratch ------------------------------------
__device__ __nv_bfloat16 g_xhi[16384 * 512];
__device__ __nv_bfloat16 g_xlo[16384 * 512];
__device__ __nv_bfloat16 g_whi[512 * 512];
__device__ __nv_bfloat16 g_wlo[512 * 512];
__device__ float         g_tmp[16384 * 512];
__device__ __nv_bfloat16 g_qhi[16384 * 512];
__device__ __nv_bfloat16 g_qlo[16384 * 512];
__device__ __nv_bfloat16 g_khi[16384 * 512];
__device__ __nv_bfloat16 g_klo[16384 * 512];
__device__ __nv_bfloat16 g_vthi[(size_t)4 * 512 * 4096];
__device__ __nv_bfloat16 g_vtlo[(size_t)4 * 512 * 4096];
__device__ float         g_s[(size_t)4 * 4096 * 4096];
__device__ __nv_bfloat16 g_phi[(size_t)4 * 4096 * 4096];
__device__ __nv_bfloat16 g_plo[(size_t)4 * 4096 * 4096];

// ----------------------------- helpers -------------------------------------
__device__ __forceinline__ uint32_t smem_u32(const void* p) {
    uint32_t a;
    asm("{ .reg .u64 t; cvta.to.shared.u64 t, %1; cvt.u32.u64 %0, t; }" : "=r"(a) : "l"(p));
    return a;
}
__device__ __forceinline__ void cpa16(uint32_t s, const void* g) {
    asm volatile("cp.async.cg.shared.global [%0], [%1], 16;" :: "r"(s), "l"(g) : "memory");
}
__device__ __forceinline__ void cp_commit() {
    asm volatile("cp.async.commit_group;" ::: "memory");
}
__device__ __forceinline__ void cp_wait1() {
    asm volatile("cp.async.wait_group 1;" ::: "memory");
}
__device__ __forceinline__ void ldm4(uint32_t* r, uint32_t a) {
    asm volatile("ldmatrix.sync.aligned.m8n8.x4.shared.b16 {%0,%1,%2,%3}, [%4];"
                 : "=r"(r[0]), "=r"(r[1]), "=r"(r[2]), "=r"(r[3]) : "r"(a));
}
__device__ __forceinline__ void mma16816(float* d, const uint32_t* a, const uint32_t* b) {
    asm volatile(
        "mma.sync.aligned.m16n8k16.row.col.f32.bf16.bf16.f32 "
        "{%0,%1,%2,%3}, {%4,%5,%6,%7}, {%8,%9}, {%0,%1,%2,%3};"
        : "+f"(d[0]), "+f"(d[1]), "+f"(d[2]), "+f"(d[3])
        : "r"(a[0]), "r"(a[1]), "r"(a[2]), "r"(a[3]), "r"(b[0]), "r"(b[1]));
}
// tile layout: 128 rows x 32 bf16 (64B/row); 16B granules xor-swizzled so
// ldmatrix 8-row phases and cp.async writes are (near) conflict-free.
__device__ __forceinline__ uint32_t swaddr(int r, int k16) {
    return (uint32_t)(r * 64 + ((k16 ^ ((r >> 1) & 3)) << 4));
}
__device__ __forceinline__ uint32_t pack2(__nv_bfloat16 a, __nv_bfloat16 b) {
    __nv_bfloat162 t(a, b);
    return *reinterpret_cast<uint32_t*>(&t);
}

// ----------------------------- split fp32 -> hi/lo bf16 ---------------------
__global__ __launch_bounds__(256)
void split2(const float4* __restrict__ x, uint2* __restrict__ hi, uint2* __restrict__ lo, int n4) {
    int i = blockIdx.x * 256 + threadIdx.x;
    if (i >= n4) return;
    float4 v = x[i];
    __nv_bfloat16 hx = __float2bfloat16(v.x), hy = __float2bfloat16(v.y);
    __nv_bfloat16 hz = __float2bfloat16(v.z), hw = __float2bfloat16(v.w);
    __nv_bfloat16 lx = __float2bfloat16(v.x - __bfloat162float(hx));
    __nv_bfloat16 ly = __float2bfloat16(v.y - __bfloat162float(hy));
    __nv_bfloat16 lz = __float2bfloat16(v.z - __bfloat162float(hz));
    __nv_bfloat16 lw = __float2bfloat16(v.w - __bfloat162float(hw));
    hi[i] = make_uint2(pack2(hx, hy), pack2(hz, hw));
    lo[i] = make_uint2(pack2(lx, ly), pack2(lz, lw));
}

// ----------------------------- V transpose + split ---------------------------
__global__ __launch_bounds__(256)
void transpose_split(const float* __restrict__ V,
                     __nv_bfloat16* __restrict__ th, __nv_bfloat16* __restrict__ tl) {
    __shared__ float t[32][33];
    long z = blockIdx.z;
    const float* Vb = V + z * 4096L * 512;
    __nv_bfloat16* thb = th + z * 512L * 4096;
    __nv_bfloat16* tlb = tl + z * 512L * 4096;
    int s0 = blockIdx.x * 32, e0 = blockIdx.y * 32;
    int tx = threadIdx.x & 31, ty = threadIdx.x >> 5;
    #pragma unroll
    for (int j = 0; j < 32; j += 8)
        t[ty + j][tx] = Vb[(long)(s0 + ty + j) * 512 + e0 + tx];
    __syncthreads();
    #pragma unroll
    for (int j = 0; j < 32; j += 8) {
        float v = t[tx][ty + j];
        __nv_bfloat16 h = __float2bfloat16(v);
        long o = (long)(e0 + ty + j) * 4096 + s0 + tx;
        thb[o] = h;
        tlb[o] = __float2bfloat16(v - __bfloat162float(h));
    }
}

// ----------------------------- split GEMM (mma.sync) -------------------------
// C = (Ah+Al)[M,K] @ (Bh+Bl)[N,K]^T (+bias); 3-term: AhBh + AhBl + AlBh.
// Output: fp32 to Cf if non-null, else bf16 hi/lo to Chi/Clo. Batch via z.
// M,N multiples of 128; K multiple of 32 (>=64).
__global__ void __launch_bounds__(256, 1)
mma_gemm(const __nv_bfloat16* __restrict__ Ah, const __nv_bfloat16* __restrict__ Al,
         const __nv_bfloat16* __restrict__ Bh, const __nv_bfloat16* __restrict__ Bl,
         const float* __restrict__ bias,
         float* __restrict__ Cf, __nv_bfloat16* __restrict__ Chi, __nv_bfloat16* __restrict__ Clo,
         int M, int N, int K, long sA, long sB, long sC)
{
    extern __shared__ char smem[];
    const uint32_t sb = smem_u32(smem);
    const int tid = threadIdx.x;
    const int lane = tid & 31, warp = tid >> 5;
    const int wm = warp >> 1, wn = warp & 1;

    const long z = blockIdx.z;
    const uint4* gAh = reinterpret_cast<const uint4*>(Ah + z * sA);
    const uint4* gAl = reinterpret_cast<const uint4*>(Al + z * sA);
    const uint4* gBh = reinterpret_cast<const uint4*>(Bh + z * sB);
    const uint4* gBl = reinterpret_cast<const uint4*>(Bl + z * sB);

    const int row0 = blockIdx.y * 128, col0 = blockIdx.x * 128;
    const int kq = K >> 3;          // uint4 per row
    const int nch = K >> 5;         // 32-elem chunks

    // tile offsets within a stage: Ah=0, Al=8K, Bh=16K, Bl=24K
    auto fill = [&](int stage, int c) {
        uint32_t base = sb + stage * 32768;
        #pragma unroll
        for (int h = 0; h < 2; h++) {
            int G = tid + h * 256;            // 512 granules of 16B per tile
            int r = G >> 2, k16 = G & 3;
            uint32_t so = swaddr(r, k16);
            long ga = (long)(row0 + r) * kq + c * 4 + k16;
            long gb = (long)(col0 + r) * kq + c * 4 + k16;
            cpa16(base +     0 + so, gAh + ga);
            cpa16(base +  8192 + so, gAl + ga);
            cpa16(base + 16384 + so, gBh + gb);
            cpa16(base + 24576 + so, gBl + gb);
        }
    };

    float acc[2][8][4];
    #pragma unroll
    for (int i = 0; i < 2; i++)
        #pragma unroll
        for (int j = 0; j < 8; j++)
            #pragma unroll
            for (int q = 0; q < 4; q++) acc[i][j][q] = 0.f;

    fill(0, 0); cp_commit();
    fill(1, 1); cp_commit();

    for (int c = 0; c < nch; c++) {
        cp_wait1();
        __syncthreads();
        // prefetch chunk c+2 into the stage freed by chunk c-1 (3-stage ring)
        if (c + 2 < nch) fill((c + 2) % NSTAGE, c + 2);
        cp_commit();

        const uint32_t base = sb + (c % NSTAGE) * 32768;
        #pragma unroll
        for (int ks = 0; ks < 2; ks++) {
            uint32_t afh[2][4], afl[2][4];
            #pragma unroll
            for (int mt = 0; mt < 2; mt++) {
                int row = wm * 32 + mt * 16 + (lane & 15);
                int kg = ks * 2 + (lane >> 4);
                uint32_t so = swaddr(row, kg);
                ldm4(afh[mt], base + so);
                ldm4(afl[mt], base + 8192 + so);
            }
            uint32_t bfh[8][2], bfl[8][2];
            #pragma unroll
            for (int p = 0; p < 4; p++) {
                int rowB = wn * 64 + p * 16 + ((lane >> 4) & 1) * 8 + (lane & 7);
                int kg = ks * 2 + ((lane >> 3) & 1);
                uint32_t so = swaddr(rowB, kg);
                uint32_t r4[4];
                ldm4(r4, base + 16384 + so);
                bfh[p * 2][0] = r4[0]; bfh[p * 2][1] = r4[1];
                bfh[p * 2 + 1][0] = r4[2]; bfh[p * 2 + 1][1] = r4[3];
                ldm4(r4, base + 24576 + so);
                bfl[p * 2][0] = r4[0]; bfl[p * 2][1] = r4[1];
                bfl[p * 2 + 1][0] = r4[2]; bfl[p * 2 + 1][1] = r4[3];
            }
            #pragma unroll
            for (int mt = 0; mt < 2; mt++)
                #pragma unroll
                for (int nt = 0; nt < 8; nt++) {
                    mma16816(acc[mt][nt], afh[mt], bfh[nt]);
                    mma16816(acc[mt][nt], afh[mt], bfl[nt]);
                    mma16816(acc[mt][nt], afl[mt], bfh[nt]);
                }
        }
        __syncthreads();
    }

    // epilogue
    #pragma unroll
    for (int mt = 0; mt < 2; mt++)
        #pragma unroll
        for (int h2 = 0; h2 < 2; h2++) {
            int r = row0 + wm * 32 + mt * 16 + (lane >> 2) + h2 * 8;
            #pragma unroll
            for (int nt = 0; nt < 8; nt++) {
                int cc = col0 + wn * 64 + nt * 8 + (lane & 3) * 2;
                float v0 = acc[mt][nt][h2 * 2 + 0];
                float v1 = acc[mt][nt][h2 * 2 + 1];
                if (bias) { v0 += __ldg(&bias[cc]); v1 += __ldg(&bias[cc + 1]); }
                if (Cf) {
                    float2 w; w.x = v0; w.y = v1;
                    *reinterpret_cast<float2*>(Cf + z * sC + (long)r * N + cc) = w;
                } else {
                    __nv_bfloat16 h0 = __float2bfloat16(v0), h1 = __float2bfloat16(v1);
                    __nv_bfloat16 l0 = __float2bfloat16(v0 - __bfloat162float(h0));
                    __nv_bfloat16 l1 = __float2bfloat16(v1 - __bfloat162float(h1));
                    long o = z * sC + (long)r * N + cc;
                    *reinterpret_cast<uint32_t*>(Chi + o) = pack2(h0, h1);
                    *reinterpret_cast<uint32_t*>(Clo + o) = pack2(l0, l1);
                }
            }
        }
}

// ----------------------------- softmax rows + split to bf16 hi/lo ------------
__global__ __launch_bounds__(256)
void softmax_split(const float* __restrict__ S,
                   __nv_bfloat16* __restrict__ PH, __nv_bfloat16* __restrict__ PL)
{
    const long row = blockIdx.x;
    const float4* p = reinterpret_cast<const float4*>(S + row * 4096L);
    const int t = threadIdx.x;

    float4 v[4];
    float m = -1e30f;
    #pragma unroll
    for (int i = 0; i < 4; i++) {
        v[i] = p[t + i * 256];
        m = fmaxf(m, fmaxf(fmaxf(v[i].x, v[i].y), fmaxf(v[i].z, v[i].w)));
    }
    __shared__ float red[256];
    red[t] = m;
    __syncthreads();
    #pragma unroll
    for (int s = 128; s > 0; s >>= 1) {
        if (t < s) red[t] = fmaxf(red[t], red[t + s]);
        __syncthreads();
    }
    m = red[0];
    __syncthreads();

    float sum = 0.f;
    #pragma unroll
    for (int i = 0; i < 4; i++) {
        v[i].x = __expf(v[i].x - m); v[i].y = __expf(v[i].y - m);
        v[i].z = __expf(v[i].z - m); v[i].w = __expf(v[i].w - m);
        sum += (v[i].x + v[i].y) + (v[i].z + v[i].w);
    }
    red[t] = sum;
    __syncthreads();
    #pragma unroll
    for (int s = 128; s > 0; s >>= 1) {
        if (t < s) red[t] += red[t + s];
        __syncthreads();
    }
    const float inv = 1.0f / red[0];

    uint2* ph = reinterpret_cast<uint2*>(PH + row * 4096L);
    uint2* pl = reinterpret_cast<uint2*>(PL + row * 4096L);
    #pragma unroll
    for (int i = 0; i < 4; i++) {
        float a = v[i].x * inv, b = v[i].y * inv, cc = v[i].z * inv, d = v[i].w * inv;
        __nv_bfloat16 ha = __float2bfloat16(a), hb = __float2bfloat16(b);
        __nv_bfloat16 hc = __float2bfloat16(cc), hd = __float2bfloat16(d);
        __nv_bfloat16 la = __float2bfloat16(a - __bfloat162float(ha));
        __nv_bfloat16 lb = __float2bfloat16(b - __bfloat162float(hb));
        __nv_bfloat16 lc = __float2bfloat16(cc - __bfloat162float(hc));
        __nv_bfloat16 ld = __float2bfloat16(d - __bfloat162float(hd));
        ph[t + i * 256] = make_uint2(pack2(ha, hb), pack2(hc, hd));
        pl[t + i * 256] = make_uint2(pack2(la, lb), pack2(lc, ld));
    }
}

// ----------------------------- launch ---------------------------------------
extern "C" void kernel_launch(void* const* d_in, const int* in_sizes, int n_in,
                              void* d_out, int out_size)
{
    const float* query = (const float*)d_in[0];
    const float* key   = (const float*)d_in[1];
    const float* value = (const float*)d_in[2];
    const float* Wq    = (const float*)d_in[3];
    const float* bq    = (const float*)d_in[4];
    const float* Wk    = (const float*)d_in[5];
    const float* bk    = (const float*)d_in[6];
    const float* Wv    = (const float*)d_in[7];
    const float* bv    = (const float*)d_in[8];
    float* out = (float*)d_out;

    __nv_bfloat16 *xhi, *xlo, *whi, *wlo, *qhi, *qlo, *khi, *klo, *vthi, *vtlo, *phi, *plo;
    float *tmp, *sp;
    cudaGetSymbolAddress((void**)&xhi, g_xhi);  cudaGetSymbolAddress((void**)&xlo, g_xlo);
    cudaGetSymbolAddress((void**)&whi, g_whi);  cudaGetSymbolAddress((void**)&wlo, g_wlo);
    cudaGetSymbolAddress((void**)&tmp, g_tmp);
    cudaGetSymbolAddress((void**)&qhi, g_qhi);  cudaGetSymbolAddress((void**)&qlo, g_qlo);
    cudaGetSymbolAddress((void**)&khi, g_khi);  cudaGetSymbolAddress((void**)&klo, g_klo);
    cudaGetSymbolAddress((void**)&vthi, g_vthi); cudaGetSymbolAddress((void**)&vtlo, g_vtlo);
    cudaGetSymbolAddress((void**)&sp, g_s);
    cudaGetSymbolAddress((void**)&phi, g_phi);  cudaGetSymbolAddress((void**)&plo, g_plo);

    static int smem_set = 0;
    if (!smem_set) {
        cudaFuncSetAttribute(mma_gemm, cudaFuncAttributeMaxDynamicSharedMemorySize, SMEM_BYTES);
        smem_set = 1;
    }

    const int S = 4096, E = 512, Btot = 4;
    const int M = Btot * S;            // 16384
    const int nX4 = M * E / 4;
    const int nW4 = E * E / 4;

    dim3 t256(256);
    dim3 gX(nX4 / 256), gW(nW4 / 256);
    dim3 gProj(E / 128, M / 128, 1);

    // --- Q projection (bf16 hi/lo out, fused) ---
    split2<<<gX, t256>>>((const float4*)query, (uint2*)xhi, (uint2*)xlo, nX4);
    split2<<<gW, t256>>>((const float4*)Wq,    (uint2*)whi, (uint2*)wlo, nW4);
    mma_gemm<<<gProj, t256, SMEM_BYTES>>>(xhi, xlo, whi, wlo, bq,
                                          nullptr, qhi, qlo, M, E, E, 0, 0, 0);
    // --- K projection ---
    split2<<<gX, t256>>>((const float4*)key, (uint2*)xhi, (uint2*)xlo, nX4);
    split2<<<gW, t256>>>((const float4*)Wk,  (uint2*)whi, (uint2*)wlo, nW4);
    mma_gemm<<<gProj, t256, SMEM_BYTES>>>(xhi, xlo, whi, wlo, bk,
                                          nullptr, khi, klo, M, E, E, 0, 0, 0);
    // --- V projection (fp32) + transpose-split ---
    split2<<<gX, t256>>>((const float4*)value, (uint2*)xhi, (uint2*)xlo, nX4);
    split2<<<gW, t256>>>((const float4*)Wv,    (uint2*)whi, (uint2*)wlo, nW4);
    mma_gemm<<<gProj, t256, SMEM_BYTES>>>(xhi, xlo, whi, wlo, bv,
                                          tmp, nullptr, nullptr, M, E, E, 0, 0, 0);
    {
        dim3 gT(S / 32, E / 32, Btot);
        transpose_split<<<gT, t256>>>(tmp, vthi, vtlo);
    }

    // --- scores = q @ k^T (fp32) ---
    {
        dim3 g(S / 128, S / 128, Btot);
        mma_gemm<<<g, t256, SMEM_BYTES>>>(qhi, qlo, khi, klo, nullptr,
                                          sp, nullptr, nullptr,
                                          S, S, E, (long)S * E, (long)S * E, (long)S * S);
    }

    // --- softmax + split P ---
    softmax_split<<<M, t256>>>(sp, phi, plo);

    // --- out = P @ V  (B = V^T [E,S] K-major) ---
    {
        dim3 g(E / 128, S / 128, Btot);
        mma_gemm<<<g, t256, SMEM_BYTES>>>(phi, plo, vthi, vtlo, nullptr,
                                          out, nullptr, nullptr,
                                          S, E, S, (long)S * S, (long)E * S, (long)S * E);
    }
}